// round 15
// baseline (speedup 1.0000x reference)
#include <cuda_runtime.h>
#include <cuda_bf16.h>
#include <cstdint>

#define BATCH 8
#define NSEED 2048
#define KPTS  16384
#define DIM   768
#define CH    256
#define BNS   (BATCH*NSEED)
#define NFS   (BATCH*CH*NSEED)
#define COLS_T 32
#define THREADS 512
#define NKS_PH 48     // proj hi/lo ksteps (K = 768)
#define NKS_AH 16     // adapter hi/lo ksteps (K = 256)
#define NTILES 4
#define NSPLIT 8
#define PREP_ITEMS (256*768 + 2*256*256)
#define PREP_BLOCKS (PREP_ITEMS/256)

typedef unsigned short ushort_t;

// -------------------- device scratch --------------------
__device__ float g_bestd[NSPLIT*BNS];
__device__ int   g_besti[NSPLIT*BNS];
__device__ float g_loss;
__device__ ushort_t g_Aph[16*NKS_PH*32*4*2];
__device__ ushort_t g_Apl[16*NKS_PH*32*4*2];
__device__ ushort_t g_A1h[16*NKS_AH*32*4*2];
__device__ ushort_t g_A1l[16*NKS_AH*32*4*2];
__device__ ushort_t g_A2h[16*NKS_AH*32*4*2];
__device__ ushort_t g_A2l[16*NKS_AH*32*4*2];

// -------------------- helpers --------------------
__device__ __forceinline__ void split_hilo(float x, ushort_t& h, ushort_t& l) {
    __nv_bfloat16 hb = __float2bfloat16(x);
    __nv_bfloat16 lb = __float2bfloat16(x - __bfloat162float(hb));
    h = __bfloat16_as_ushort(hb);
    l = __bfloat16_as_ushort(lb);
}
__device__ __forceinline__ unsigned long long pack2(float a, float b) {
    unsigned long long r;
    asm("mov.b64 %0, {%1, %2};" : "=l"(r) : "r"(__float_as_uint(a)), "r"(__float_as_uint(b)));
    return r;
}
__device__ __forceinline__ float2 unpack2(unsigned long long v) {
    unsigned int lo, hi;
    asm("mov.b64 {%0, %1}, %2;" : "=r"(lo), "=r"(hi) : "l"(v));
    return make_float2(__uint_as_float(lo), __uint_as_float(hi));
}
__device__ __forceinline__ unsigned long long fma2(unsigned long long a,
                                                   unsigned long long b,
                                                   unsigned long long c) {
    unsigned long long d;
    asm("fma.rn.f32x2 %0, %1, %2, %3;" : "=l"(d) : "l"(a), "l"(b), "l"(c));
    return d;
}

// fragment index for slot s (= dim), output row o
__device__ __forceinline__ size_t aidx_h(int o, int s, int nks) {
    int kstep = s >> 4, ks = s & 15;
    int mtile = o >> 4, mm = o & 15;
    int lane = (mm & 7) * 4 + ((ks >> 1) & 3);
    int word = ((mm >> 3) & 1) + 2 * ((ks >> 3) & 1);
    int half = ks & 1;
    return ((((size_t)mtile * nks + kstep) * 32 + lane) * 4 + word) * 2 + half;
}
__device__ __forceinline__ int bidx_h(int s, int n) {
    int kstep = s >> 4, ks = s & 15;
    int nt = n >> 3, np = nt >> 1, ntip = nt & 1;
    int lane = (n & 7) * 4 + ((ks >> 1) & 3);
    int wk = (ks >> 3) & 1;
    int half = ks & 1;
    return (((kstep * 2 + np) * 32 + lane) * 4 + (ntip * 2 + wk)) * 2 + half;
}
// write hi/lo of one value into the two B arrays (same index)
__device__ __forceinline__ void put2(ushort_t* bh, ushort_t* bl, int row, int col, float v) {
    ushort_t h, l; split_hilo(v, h, l);
    int ix = bidx_h(row, col);
    bh[ix] = h;
    bl[ix] = l;
}

// -------------------- weight prep (+ loss zero) --------------------
__global__ __launch_bounds__(256) void k_prep(
    const float* __restrict__ Wp, const float* __restrict__ Wa1, const float* __restrict__ Wa2)
{
    int id = blockIdx.x * 256 + threadIdx.x;
    if (id == 0) g_loss = 0.0f;
    ushort_t h, l;
    if (id < 256*768) {
        int o = id / 768, d = id % 768;
        split_hilo(Wp[id], h, l);
        size_t ix = aidx_h(o, d, NKS_PH);
        g_Aph[ix] = h; g_Apl[ix] = l;
    } else if (id < 256*768 + 256*256) {
        int t = id - 256*768; int o = t >> 8, d = t & 255;
        split_hilo(Wa1[t], h, l);
        size_t ix = aidx_h(o, d, NKS_AH);
        g_A1h[ix] = h; g_A1l[ix] = l;
    } else if (id < PREP_ITEMS) {
        int t = id - 256*768 - 256*256; int o = t >> 8, d = t & 255;
        split_hilo(Wa2[t], h, l);
        size_t ix = aidx_h(o, d, NKS_AH);
        g_A2h[ix] = h; g_A2l[ix] = l;
    }
}

// -------------------- kernel 1: argmin (group-min + equality rescan) --------------------
__global__ __launch_bounds__(128) void k_argmin(
    const float* __restrict__ seed, const float* __restrict__ pts)
{
    __shared__ float4 tA[1024], tB[1024];
    int gs = blockIdx.x * 128 + threadIdx.x;
    int b  = gs >> 11;
    int kbase = blockIdx.y * 2048;
    const float* pb = pts + ((size_t)b * KPTS + kbase) * 3;

    float sx = seed[gs*3+0], sy = seed[gs*3+1], sz = seed[gs*3+2];
    unsigned long long mxx = pack2(-2.0f*sx, -2.0f*sx);
    unsigned long long myy = pack2(-2.0f*sy, -2.0f*sy);
    unsigned long long mzz = pack2(-2.0f*sz, -2.0f*sz);

    for (int p = threadIdx.x; p < 1024; p += 128) {
        const float* q = pb + 6*p;
        float x0=q[0], y0=q[1], z0=q[2], x1=q[3], y1=q[4], z1=q[5];
        tA[p] = make_float4(x0, x1, y0, y1);
        tB[p] = make_float4(z0, z1, x0*x0+y0*y0+z0*z0, x1*x1+y1*y1+z1*z1);
    }
    __syncthreads();

    float bd = 1e30f;
    int gwin = 0;
    #pragma unroll 1
    for (int g = 0; g < 16; ++g) {
        float gbd = bd;
        const float4* pA = tA + g*64;
        const float4* pB = tB + g*64;
        #pragma unroll 8
        for (int it = 0; it < 64; ++it) {
            float4 A = pA[it], B = pB[it];
            unsigned long long d2 =
                fma2(mxx, pack2(A.x, A.y),
                fma2(myy, pack2(A.z, A.w),
                fma2(mzz, pack2(B.x, B.y), pack2(B.z, B.w))));
            float2 d = unpack2(d2);
            gbd = fminf(gbd, fminf(d.x, d.y));
        }
        if (gbd < bd) { bd = gbd; gwin = g; }
    }

    int lane = threadIdx.x & 31;
    int mi = 0x7fffffff;
    int base = gwin * 64;
    #pragma unroll 8
    for (int it = 0; it < 64; ++it) {
        int p = base + ((it + lane) & 63);
        float4 A = tA[p], B = tB[p];
        unsigned long long d2 =
            fma2(mxx, pack2(A.x, A.y),
            fma2(myy, pack2(A.z, A.w),
            fma2(mzz, pack2(B.x, B.y), pack2(B.z, B.w))));
        float2 d = unpack2(d2);
        if (d.x == bd) mi = min(mi, 2*p);
        if (d.y == bd) mi = min(mi, 2*p + 1);
    }
    g_bestd[blockIdx.y * BNS + gs] = bd;
    g_besti[blockIdx.y * BNS + gs] = kbase + mi;
}

// -------------------- mma helpers --------------------
__device__ __forceinline__ void mma16816(float* c, const uint4& a, unsigned b0, unsigned b1) {
    asm volatile(
        "mma.sync.aligned.m16n8k16.row.col.f32.bf16.bf16.f32 "
        "{%0,%1,%2,%3}, {%4,%5,%6,%7}, {%8,%9}, {%0,%1,%2,%3};"
        : "+f"(c[0]), "+f"(c[1]), "+f"(c[2]), "+f"(c[3])
        : "r"(a.x), "r"(a.y), "r"(a.z), "r"(a.w), "r"(b0), "r"(b1));
}
// hi-pass: one A_hi fragment vs B_hi and B_lo -> 8 MMAs per A-load.
// Ring-buffer depth-8 prefetch: a[j] reloaded 8 ksteps before its reuse.
__device__ __forceinline__ void span_hi(float acc[16],
    const uint4* __restrict__ Aw, const uint4* __restrict__ Bh,
    const uint4* __restrict__ Bl, int nks)
{
    uint4 a[8];
    #pragma unroll
    for (int j = 0; j < 8; ++j) a[j] = Aw[(size_t)j * 32];
    #pragma unroll
    for (int ks = 0; ks < 16; ++ks) {
        int j = ks & 7;
        uint4 av = a[j];
        if (ks + 8 < 16) a[j] = Aw[(size_t)(ks + 8) * 32];
        uint4 b0 = Bh[(ks*2 + 0) * 32];
        mma16816(acc + 0,  av, b0.x, b0.y);
        mma16816(acc + 4,  av, b0.z, b0.w);
        uint4 b1 = Bh[(ks*2 + 1) * 32];
        mma16816(acc + 8,  av, b1.x, b1.y);
        mma16816(acc + 12, av, b1.z, b1.w);
        uint4 c0 = Bl[(ks*2 + 0) * 32];
        mma16816(acc + 0,  av, c0.x, c0.y);
        mma16816(acc + 4,  av, c0.z, c0.w);
        uint4 c1 = Bl[(ks*2 + 1) * 32];
        mma16816(acc + 8,  av, c1.x, c1.y);
        mma16816(acc + 12, av, c1.z, c1.w);
    }
    (void)nks;
}
// lo-pass: A_lo vs B_hi only; same ring prefetch
__device__ __forceinline__ void span_lo(float acc[16],
    const uint4* __restrict__ Aw, const uint4* __restrict__ Bh, int nks)
{
    uint4 a[8];
    #pragma unroll
    for (int j = 0; j < 8; ++j) a[j] = Aw[(size_t)j * 32];
    #pragma unroll
    for (int ks = 0; ks < 16; ++ks) {
        int j = ks & 7;
        uint4 av = a[j];
        if (ks + 8 < 16) a[j] = Aw[(size_t)(ks + 8) * 32];
        uint4 b0 = Bh[(ks*2 + 0) * 32];
        mma16816(acc + 0,  av, b0.x, b0.y);
        mma16816(acc + 4,  av, b0.z, b0.w);
        uint4 b1 = Bh[(ks*2 + 1) * 32];
        mma16816(acc + 8,  av, b1.x, b1.y);
        mma16816(acc + 12, av, b1.z, b1.w);
    }
    (void)nks;
}

// -------------------- smem layout (bytes) --------------------
#define SMB_B0H  0
#define SMB_B0L  16384
#define SMB_B1H  32768
#define SMB_B1L  49152
#define SMB_REDS 65536
#define SMB_REDQ 67584
#define SMB_MU   69632
#define SMB_RS   69760
#define SMEM_BYTES 69888

// -------------------- kernel 2: fused --------------------
__global__ void __launch_bounds__(THREADS, 1) k_fused(
    const float* __restrict__ feat, const float* __restrict__ f_teacher,
    const float* __restrict__ b_proj, const float* __restrict__ b_a1,
    const float* __restrict__ b_a2,
    float* __restrict__ out, int out_size)
{
    extern __shared__ char smraw[];
    ushort_t* b0h = (ushort_t*)(smraw + SMB_B0H);
    ushort_t* b0l = (ushort_t*)(smraw + SMB_B0L);
    ushort_t* b1h = (ushort_t*)(smraw + SMB_B1H);
    ushort_t* b1l = (ushort_t*)(smraw + SMB_B1L);
    float* red_s = (float*)(smraw + SMB_REDS);
    float* red_q = (float*)(smraw + SMB_REDQ);
    float* smu   = (float*)(smraw + SMB_MU);
    float* srs   = (float*)(smraw + SMB_RS);

    int tid  = threadIdx.x;
    int lane = tid & 31;
    int wid  = tid >> 5;
    int j0   = blockIdx.x * COLS_T;
    int b    = j0 >> 11;
    int ns0  = j0 & 2047;

    // per-thread split-K merge (no barrier)
    int mycol = tid & 31;
    int drow  = tid >> 5;
    int bi;
    {
        int gs = j0 + mycol;
        float bd = g_bestd[gs];
        bi = g_besti[gs];
        #pragma unroll
        for (int y = 1; y < NSPLIT; ++y) {
            float d2 = g_bestd[y*BNS + gs];
            int   i2 = g_besti[y*BNS + gs];
            if (d2 < bd || (d2 == bd && i2 < bi)) { bd = d2; bi = i2; }
        }
    }
    const float* featb = feat + (size_t)b * DIM * KPTS;
    const float* gbase = featb + bi;

    // chunk 0 gather -> b0h/b0l
    {
        float v[16];
        #pragma unroll
        for (int t = 0; t < 16; ++t)
            v[t] = __ldg(gbase + (size_t)(drow + t*16) * KPTS);
        #pragma unroll
        for (int t = 0; t < 16; ++t)
            put2(b0h, b0l, drow + t*16, mycol, v[t]);
    }
    __syncthreads();

    int r  = lane >> 2;
    int c2 = (lane & 3) * 2;
    int m0 = wid * 16;

    float acc[16];
    #pragma unroll
    for (int p = 0; p < 16; ++p) acc[p] = 0.0f;

    const uint4* Aph = (const uint4*)g_Aph + ((size_t)wid*NKS_PH*32 + lane);
    const uint4* Apl = (const uint4*)g_Apl + ((size_t)wid*NKS_PH*32 + lane);
    const uint4* B0h = (const uint4*)b0h + lane;
    const uint4* B0l = (const uint4*)b0l + lane;
    const uint4* B1h = (const uint4*)b1h + lane;
    const uint4* B1l = (const uint4*)b1l + lane;

    // projection: 3 chunks of 256 dims (16 hi + 16 lo ksteps), pipelined gather
    #pragma unroll 1
    for (int c = 0; c < 3; ++c) {
        const uint4* Bh = (c & 1) ? B1h : B0h;
        const uint4* Bl = (c & 1) ? B1l : B0l;
        ushort_t* nh = (c & 1) ? b0h : b1h;
        ushort_t* nl = (c & 1) ? b0l : b1l;
        bool more = (c < 2);
        int nb = (c+1)*256;
        float st[8];
        if (more) {
            #pragma unroll
            for (int t = 0; t < 8; ++t)
                st[t] = __ldg(gbase + (size_t)(nb + drow + t*16) * KPTS);
        }
        span_hi(acc, Aph + (size_t)c*16*32, Bh, Bl, 16);
        if (more) {
            #pragma unroll
            for (int t = 0; t < 8; ++t)
                put2(nh, nl, drow + t*16, mycol, st[t]);
            #pragma unroll
            for (int t = 0; t < 8; ++t)
                st[t] = __ldg(gbase + (size_t)(nb + drow + (8+t)*16) * KPTS);
        }
        span_lo(acc, Apl + (size_t)c*16*32, Bh, 16);
        if (more) {
            #pragma unroll
            for (int t = 0; t < 8; ++t)
                put2(nh, nl, drow + (8+t)*16, mycol, st[t]);
        }
        __syncthreads();
    }

    // bias + LN stats
    {
        float bb0 = __ldg(b_proj + m0 + r);
        float bb1 = __ldg(b_proj + m0 + r + 8);
        #pragma unroll
        for (int nt = 0; nt < NTILES; ++nt) {
            acc[nt*4+0] += bb0; acc[nt*4+1] += bb0;
            acc[nt*4+2] += bb1; acc[nt*4+3] += bb1;
        }
    }
    {
        float s[8], q[8];
        #pragma unroll
        for (int nt = 0; nt < NTILES; ++nt) {
            s[nt*2+0] = acc[nt*4+0] + acc[nt*4+2];
            s[nt*2+1] = acc[nt*4+1] + acc[nt*4+3];
            q[nt*2+0] = acc[nt*4+0]*acc[nt*4+0] + acc[nt*4+2]*acc[nt*4+2];
            q[nt*2+1] = acc[nt*4+1]*acc[nt*4+1] + acc[nt*4+3]*acc[nt*4+3];
        }
        #pragma unroll
        for (int off = 4; off < 32; off <<= 1) {
            #pragma unroll
            for (int u = 0; u < 8; ++u) {
                s[u] += __shfl_xor_sync(0xffffffffu, s[u], off);
                q[u] += __shfl_xor_sync(0xffffffffu, q[u], off);
            }
        }
        if (lane < 4) {
            #pragma unroll
            for (int nt = 0; nt < NTILES; ++nt) {
                int col = nt*8 + lane*2;
                red_s[col*16 + wid]     = s[nt*2+0];
                red_s[(col+1)*16 + wid] = s[nt*2+1];
                red_q[col*16 + wid]     = q[nt*2+0];
                red_q[(col+1)*16 + wid] = q[nt*2+1];
            }
        }
    }
    __syncthreads();
    if (tid < COLS_T) {
        float S = 0.0f, Q = 0.0f;
        #pragma unroll
        for (int mt = 0; mt < 16; ++mt) { S += red_s[tid*16+mt]; Q += red_q[tid*16+mt]; }
        float mu  = S * (1.0f/256.0f);
        float var = Q * (1.0f/256.0f) - mu*mu;
        smu[tid] = mu;
        srs[tid] = rsqrtf(var + 1e-5f);
    }
    __syncthreads();

    // normalize -> b0h/b0l (Ba)
    #pragma unroll
    for (int nt = 0; nt < NTILES; ++nt) {
        int col = nt*8 + c2;
        float mA = smu[col],   rA = srs[col];
        float mB = smu[col+1], rB = srs[col+1];
        put2(b0h, b0l, m0+r,   col,   (acc[nt*4+0]-mA)*rA);
        put2(b0h, b0l, m0+r,   col+1, (acc[nt*4+1]-mB)*rB);
        put2(b0h, b0l, m0+r+8, col,   (acc[nt*4+2]-mA)*rA);
        put2(b0h, b0l, m0+r+8, col+1, (acc[nt*4+3]-mB)*rB);
    }
    __syncthreads();

    // adapter conv1 + ReLU -> b1h/b1l
    #pragma unroll
    for (int p = 0; p < 16; ++p) acc[p] = 0.0f;
    {
        const uint4* Ah = (const uint4*)g_A1h + ((size_t)wid*NKS_AH*32 + lane);
        const uint4* Al = (const uint4*)g_A1l + ((size_t)wid*NKS_AH*32 + lane);
        span_hi(acc, Ah, B0h, B0l, 16);
        span_lo(acc, Al, B0h, 16);
    }
    {
        float bb0 = __ldg(b_a1 + m0 + r);
        float bb1 = __ldg(b_a1 + m0 + r + 8);
        #pragma unroll
        for (int nt = 0; nt < NTILES; ++nt) {
            int col = nt*8 + c2;
            put2(b1h, b1l, m0+r,   col,   fmaxf(acc[nt*4+0]+bb0, 0.0f));
            put2(b1h, b1l, m0+r,   col+1, fmaxf(acc[nt*4+1]+bb0, 0.0f));
            put2(b1h, b1l, m0+r+8, col,   fmaxf(acc[nt*4+2]+bb1, 0.0f));
            put2(b1h, b1l, m0+r+8, col+1, fmaxf(acc[nt*4+3]+bb1, 0.0f));
        }
    }
    __syncthreads();

    // adapter conv2
    #pragma unroll
    for (int p = 0; p < 16; ++p) acc[p] = 0.0f;
    {
        const uint4* Ah = (const uint4*)g_A2h + ((size_t)wid*NKS_AH*32 + lane);
        const uint4* Al = (const uint4*)g_A2l + ((size_t)wid*NKS_AH*32 + lane);
        span_hi(acc, Ah, B1h, B1l, 16);
        span_lo(acc, Al, B1h, 16);
    }

    // bias + output + loss
    float bb0 = __ldg(b_a2 + m0 + r);
    float bb1 = __ldg(b_a2 + m0 + r + 8);
    float ls = 0.0f;
    size_t ob0 = ((size_t)b * CH + (m0 + r)) * NSEED + ns0;
    size_t ob1 = ((size_t)b * CH + (m0 + r + 8)) * NSEED + ns0;
    bool full = (NFS <= out_size);
    #pragma unroll
    for (int nt = 0; nt < NTILES; ++nt) {
        int col = nt*8 + c2;
        float f0 = acc[nt*4+0]+bb0, f1 = acc[nt*4+1]+bb0;
        float f2 = acc[nt*4+2]+bb1, f3 = acc[nt*4+3]+bb1;
        if (full) {
            *(float2*)(out + ob0 + col) = make_float2(f0, f1);
            *(float2*)(out + ob1 + col) = make_float2(f2, f3);
        }
        float2 t0 = *(const float2*)(f_teacher + ob0 + col);
        float2 t1 = *(const float2*)(f_teacher + ob1 + col);
        float d0 = f0-t0.x, d1 = f1-t0.y, d2 = f2-t1.x, d3 = f3-t1.y;
        ls += d0*d0 + d1*d1 + d2*d2 + d3*d3;
    }
    #pragma unroll
    for (int o = 16; o; o >>= 1) ls += __shfl_xor_sync(0xffffffffu, ls, o);
    if (lane == 0) atomicAdd(&g_loss, ls);
}

// -------------------- kernel 3: finalize loss --------------------
__global__ void k_final(float* __restrict__ out, int out_size)
{
    float v = g_loss * (1.0f / (float)NFS);
    if (out_size > NFS) {
        for (int i = NFS + (int)threadIdx.x; i < out_size; i += (int)blockDim.x)
            out[i] = v;
    } else if (out_size > 0 && out_size < NFS && threadIdx.x == 0) {
        out[out_size - 1] = v;
    }
}

// -------------------- launch --------------------
extern "C" void kernel_launch(void* const* d_in, const int* in_sizes, int n_in,
                              void* d_out, int out_size)
{
    (void)in_sizes; (void)n_in;
    const float* seed_xyz    = (const float*)d_in[1];
    const float* pts         = (const float*)d_in[2];
    const float* feat        = (const float*)d_in[3];
    const float* f_teacher   = (const float*)d_in[4];
    const float* W_proj      = (const float*)d_in[5];
    const float* b_proj      = (const float*)d_in[6];
    const float* W_a1        = (const float*)d_in[7];
    const float* b_a1        = (const float*)d_in[8];
    const float* W_a2        = (const float*)d_in[9];
    const float* b_a2        = (const float*)d_in[10];
    float* out = (float*)d_out;

    cudaFuncSetAttribute(k_fused, cudaFuncAttributeMaxDynamicSharedMemorySize, SMEM_BYTES);

    k_prep<<<PREP_BLOCKS, 256>>>(W_proj, W_a1, W_a2);
    dim3 g1(BNS/128, NSPLIT);
    k_argmin<<<g1, 128>>>(seed_xyz, pts);
    k_fused<<<BNS/COLS_T, THREADS, SMEM_BYTES>>>(feat, f_teacher,
                                                 b_proj, b_a1, b_a2, out, out_size);
    k_final<<<1, 64>>>(out, out_size);
}

// round 16
// speedup vs baseline: 1.0741x; 1.0741x over previous
#include <cuda_runtime.h>
#include <cuda_bf16.h>
#include <cstdint>

#define BATCH 8
#define NSEED 2048
#define KPTS  16384
#define DIM   768
#define CH    256
#define BNS   (BATCH*NSEED)
#define NFS   (BATCH*CH*NSEED)
#define COLS_T 32
#define THREADS 512
#define NKS_PH 48     // proj hi/lo ksteps (K = 768)
#define NKS_AH 16     // adapter hi/lo ksteps (K = 256)
#define NTILES 4
#define NSPLIT 8
#define PREP_ITEMS (256*768 + 2*256*256)
#define PREP_BLOCKS (PREP_ITEMS/256)

typedef unsigned short ushort_t;

// -------------------- device scratch --------------------
__device__ float g_bestd[NSPLIT*BNS];
__device__ int   g_besti[NSPLIT*BNS];
__device__ float g_loss;
__device__ ushort_t g_Aph[16*NKS_PH*32*4*2];
__device__ ushort_t g_Apl[16*NKS_PH*32*4*2];
__device__ ushort_t g_A1h[16*NKS_AH*32*4*2];
__device__ ushort_t g_A1l[16*NKS_AH*32*4*2];
__device__ ushort_t g_A2h[16*NKS_AH*32*4*2];
__device__ ushort_t g_A2l[16*NKS_AH*32*4*2];

// -------------------- helpers --------------------
__device__ __forceinline__ void split_hilo(float x, ushort_t& h, ushort_t& l) {
    __nv_bfloat16 hb = __float2bfloat16(x);
    __nv_bfloat16 lb = __float2bfloat16(x - __bfloat162float(hb));
    h = __bfloat16_as_ushort(hb);
    l = __bfloat16_as_ushort(lb);
}
__device__ __forceinline__ unsigned long long pack2(float a, float b) {
    unsigned long long r;
    asm("mov.b64 %0, {%1, %2};" : "=l"(r) : "r"(__float_as_uint(a)), "r"(__float_as_uint(b)));
    return r;
}
__device__ __forceinline__ float2 unpack2(unsigned long long v) {
    unsigned int lo, hi;
    asm("mov.b64 {%0, %1}, %2;" : "=r"(lo), "=r"(hi) : "l"(v));
    return make_float2(__uint_as_float(lo), __uint_as_float(hi));
}
__device__ __forceinline__ unsigned long long fma2(unsigned long long a,
                                                   unsigned long long b,
                                                   unsigned long long c) {
    unsigned long long d;
    asm("fma.rn.f32x2 %0, %1, %2, %3;" : "=l"(d) : "l"(a), "l"(b), "l"(c));
    return d;
}

// fragment index for slot s (= dim), output row o
__device__ __forceinline__ size_t aidx_h(int o, int s, int nks) {
    int kstep = s >> 4, ks = s & 15;
    int mtile = o >> 4, mm = o & 15;
    int lane = (mm & 7) * 4 + ((ks >> 1) & 3);
    int word = ((mm >> 3) & 1) + 2 * ((ks >> 3) & 1);
    int half = ks & 1;
    return ((((size_t)mtile * nks + kstep) * 32 + lane) * 4 + word) * 2 + half;
}
__device__ __forceinline__ int bidx_h(int s, int n) {
    int kstep = s >> 4, ks = s & 15;
    int nt = n >> 3, np = nt >> 1, ntip = nt & 1;
    int lane = (n & 7) * 4 + ((ks >> 1) & 3);
    int wk = (ks >> 3) & 1;
    int half = ks & 1;
    return (((kstep * 2 + np) * 32 + lane) * 4 + (ntip * 2 + wk)) * 2 + half;
}
// write hi/lo of one value into the two B arrays (same index)
__device__ __forceinline__ void put2(ushort_t* bh, ushort_t* bl, int row, int col, float v) {
    ushort_t h, l; split_hilo(v, h, l);
    int ix = bidx_h(row, col);
    bh[ix] = h;
    bl[ix] = l;
}

// -------------------- weight prep (+ loss zero) --------------------
__global__ __launch_bounds__(256) void k_prep(
    const float* __restrict__ Wp, const float* __restrict__ Wa1, const float* __restrict__ Wa2)
{
    int id = blockIdx.x * 256 + threadIdx.x;
    if (id == 0) g_loss = 0.0f;
    ushort_t h, l;
    if (id < 256*768) {
        int o = id / 768, d = id % 768;
        split_hilo(Wp[id], h, l);
        size_t ix = aidx_h(o, d, NKS_PH);
        g_Aph[ix] = h; g_Apl[ix] = l;
    } else if (id < 256*768 + 256*256) {
        int t = id - 256*768; int o = t >> 8, d = t & 255;
        split_hilo(Wa1[t], h, l);
        size_t ix = aidx_h(o, d, NKS_AH);
        g_A1h[ix] = h; g_A1l[ix] = l;
    } else if (id < PREP_ITEMS) {
        int t = id - 256*768 - 256*256; int o = t >> 8, d = t & 255;
        split_hilo(Wa2[t], h, l);
        size_t ix = aidx_h(o, d, NKS_AH);
        g_A2h[ix] = h; g_A2l[ix] = l;
    }
}

// -------------------- kernel 1: argmin, 256 seeds/block --------------------
__global__ __launch_bounds__(256) void k_argmin(
    const float* __restrict__ seed, const float* __restrict__ pts)
{
    __shared__ float4 tA[1024], tB[1024];
    int gs = blockIdx.x * 256 + threadIdx.x;
    int b  = gs >> 11;
    int kbase = blockIdx.y * 2048;
    const float* pb = pts + ((size_t)b * KPTS + kbase) * 3;

    float sx = seed[gs*3+0], sy = seed[gs*3+1], sz = seed[gs*3+2];
    unsigned long long mxx = pack2(-2.0f*sx, -2.0f*sx);
    unsigned long long myy = pack2(-2.0f*sy, -2.0f*sy);
    unsigned long long mzz = pack2(-2.0f*sz, -2.0f*sz);

    for (int p = threadIdx.x; p < 1024; p += 256) {
        const float* q = pb + 6*p;
        float x0=q[0], y0=q[1], z0=q[2], x1=q[3], y1=q[4], z1=q[5];
        tA[p] = make_float4(x0, x1, y0, y1);
        tB[p] = make_float4(z0, z1, x0*x0+y0*y0+z0*z0, x1*x1+y1*y1+z1*z1);
    }
    __syncthreads();

    float bd = 1e30f;
    int gwin = 0;
    #pragma unroll 1
    for (int g = 0; g < 16; ++g) {
        float gbd = bd;
        const float4* pA = tA + g*64;
        const float4* pB = tB + g*64;
        #pragma unroll 8
        for (int it = 0; it < 64; ++it) {
            float4 A = pA[it], B = pB[it];
            unsigned long long d2 =
                fma2(mxx, pack2(A.x, A.y),
                fma2(myy, pack2(A.z, A.w),
                fma2(mzz, pack2(B.x, B.y), pack2(B.z, B.w))));
            float2 d = unpack2(d2);
            gbd = fminf(gbd, fminf(d.x, d.y));
        }
        if (gbd < bd) { bd = gbd; gwin = g; }
    }

    int lane = threadIdx.x & 31;
    int mi = 0x7fffffff;
    int base = gwin * 64;
    #pragma unroll 8
    for (int it = 0; it < 64; ++it) {
        int p = base + ((it + lane) & 63);
        float4 A = tA[p], B = tB[p];
        unsigned long long d2 =
            fma2(mxx, pack2(A.x, A.y),
            fma2(myy, pack2(A.z, A.w),
            fma2(mzz, pack2(B.x, B.y), pack2(B.z, B.w))));
        float2 d = unpack2(d2);
        if (d.x == bd) mi = min(mi, 2*p);
        if (d.y == bd) mi = min(mi, 2*p + 1);
    }
    g_bestd[blockIdx.y * BNS + gs] = bd;
    g_besti[blockIdx.y * BNS + gs] = kbase + mi;
}

// -------------------- mma helpers --------------------
__device__ __forceinline__ void mma16816(float* c, const uint4& a, unsigned b0, unsigned b1) {
    asm volatile(
        "mma.sync.aligned.m16n8k16.row.col.f32.bf16.bf16.f32 "
        "{%0,%1,%2,%3}, {%4,%5,%6,%7}, {%8,%9}, {%0,%1,%2,%3};"
        : "+f"(c[0]), "+f"(c[1]), "+f"(c[2]), "+f"(c[3])
        : "r"(a.x), "r"(a.y), "r"(a.z), "r"(a.w), "r"(b0), "r"(b1));
}
// Fused hi+lo span: per kstep load Bh(b0,b1) + Bl(c0,c1) ONCE, issue 12 MMAs:
//   Whi*xhi (Bh), Whi*xlo (Bl), Wlo*xhi (Bh).  MLP-4 prefetch (2 ksteps ahead,
//   hi+lo pairs) covers L2 latency with double the issue distance of round 13.
__device__ __forceinline__ void span_hl(float acc[16],
    const uint4* __restrict__ Ah, const uint4* __restrict__ Al,
    const uint4* __restrict__ Bh, const uint4* __restrict__ Bl,
    int ks0, int ks1)
{
    uint4 ah[2], al[2];
    ah[0] = Ah[(size_t)ks0*32];       ah[1] = Ah[(size_t)(ks0+1)*32];
    al[0] = Al[(size_t)ks0*32];       al[1] = Al[(size_t)(ks0+1)*32];
    #pragma unroll 1
    for (int kb = ks0; kb < ks1; kb += 2) {
        uint4 nh[2], nl[2];
        bool more = (kb + 2) < ks1;
        if (more) {
            nh[0] = Ah[(size_t)(kb+2)*32]; nh[1] = Ah[(size_t)(kb+3)*32];
            nl[0] = Al[(size_t)(kb+2)*32]; nl[1] = Al[(size_t)(kb+3)*32];
        }
        #pragma unroll
        for (int j = 0; j < 2; ++j) {
            int ks = kb + j;
            uint4 b0 = Bh[(ks*2 + 0) * 32];
            uint4 b1 = Bh[(ks*2 + 1) * 32];
            uint4 c0 = Bl[(ks*2 + 0) * 32];
            uint4 c1 = Bl[(ks*2 + 1) * 32];
            mma16816(acc + 0,  ah[j], b0.x, b0.y);
            mma16816(acc + 4,  ah[j], b0.z, b0.w);
            mma16816(acc + 8,  ah[j], b1.x, b1.y);
            mma16816(acc + 12, ah[j], b1.z, b1.w);
            mma16816(acc + 0,  ah[j], c0.x, c0.y);
            mma16816(acc + 4,  ah[j], c0.z, c0.w);
            mma16816(acc + 8,  ah[j], c1.x, c1.y);
            mma16816(acc + 12, ah[j], c1.z, c1.w);
            mma16816(acc + 0,  al[j], b0.x, b0.y);
            mma16816(acc + 4,  al[j], b0.z, b0.w);
            mma16816(acc + 8,  al[j], b1.x, b1.y);
            mma16816(acc + 12, al[j], b1.z, b1.w);
        }
        ah[0] = nh[0]; ah[1] = nh[1];
        al[0] = nl[0]; al[1] = nl[1];
    }
}

// -------------------- smem layout (bytes) --------------------
#define SMB_B0H  0
#define SMB_B0L  16384
#define SMB_B1H  32768
#define SMB_B1L  49152
#define SMB_REDS 65536
#define SMB_REDQ 67584
#define SMB_MU   69632
#define SMB_RS   69760
#define SMEM_BYTES 69888

// -------------------- kernel 2: fused --------------------
__global__ void __launch_bounds__(THREADS, 1) k_fused(
    const float* __restrict__ feat, const float* __restrict__ f_teacher,
    const float* __restrict__ b_proj, const float* __restrict__ b_a1,
    const float* __restrict__ b_a2,
    float* __restrict__ out, int out_size)
{
    extern __shared__ char smraw[];
    ushort_t* b0h = (ushort_t*)(smraw + SMB_B0H);
    ushort_t* b0l = (ushort_t*)(smraw + SMB_B0L);
    ushort_t* b1h = (ushort_t*)(smraw + SMB_B1H);
    ushort_t* b1l = (ushort_t*)(smraw + SMB_B1L);
    float* red_s = (float*)(smraw + SMB_REDS);
    float* red_q = (float*)(smraw + SMB_REDQ);
    float* smu   = (float*)(smraw + SMB_MU);
    float* srs   = (float*)(smraw + SMB_RS);

    int tid  = threadIdx.x;
    int lane = tid & 31;
    int wid  = tid >> 5;
    int j0   = blockIdx.x * COLS_T;
    int b    = j0 >> 11;
    int ns0  = j0 & 2047;

    // per-thread split-K merge (no barrier)
    int mycol = tid & 31;
    int drow  = tid >> 5;
    int bi;
    {
        int gs = j0 + mycol;
        float bd = g_bestd[gs];
        bi = g_besti[gs];
        #pragma unroll
        for (int y = 1; y < NSPLIT; ++y) {
            float d2 = g_bestd[y*BNS + gs];
            int   i2 = g_besti[y*BNS + gs];
            if (d2 < bd || (d2 == bd && i2 < bi)) { bd = d2; bi = i2; }
        }
    }
    const float* featb = feat + (size_t)b * DIM * KPTS;
    const float* gbase = featb + bi;

    // chunk 0 gather -> b0h/b0l
    {
        float v[16];
        #pragma unroll
        for (int t = 0; t < 16; ++t)
            v[t] = __ldg(gbase + (size_t)(drow + t*16) * KPTS);
        #pragma unroll
        for (int t = 0; t < 16; ++t)
            put2(b0h, b0l, drow + t*16, mycol, v[t]);
    }
    __syncthreads();

    int r  = lane >> 2;
    int c2 = (lane & 3) * 2;
    int m0 = wid * 16;

    float acc[16];
    #pragma unroll
    for (int p = 0; p < 16; ++p) acc[p] = 0.0f;

    const uint4* Aph = (const uint4*)g_Aph + ((size_t)wid*NKS_PH*32 + lane);
    const uint4* Apl = (const uint4*)g_Apl + ((size_t)wid*NKS_PH*32 + lane);
    const uint4* B0h = (const uint4*)b0h + lane;
    const uint4* B0l = (const uint4*)b0l + lane;
    const uint4* B1h = (const uint4*)b1h + lane;
    const uint4* B1l = (const uint4*)b1l + lane;

    // projection: 3 chunks of 256 dims (16 ksteps fused hi+lo), pipelined gather
    #pragma unroll 1
    for (int c = 0; c < 3; ++c) {
        const uint4* Bh = (c & 1) ? B1h : B0h;
        const uint4* Bl = (c & 1) ? B1l : B0l;
        ushort_t* nh = (c & 1) ? b0h : b1h;
        ushort_t* nl = (c & 1) ? b0l : b1l;
        const uint4* Ah = Aph + (size_t)c*16*32;
        const uint4* Al = Apl + (size_t)c*16*32;
        bool more = (c < 2);
        int nb = (c+1)*256;
        float st[8];
        if (more) {
            #pragma unroll
            for (int t = 0; t < 8; ++t)
                st[t] = __ldg(gbase + (size_t)(nb + drow + t*16) * KPTS);
        }
        span_hl(acc, Ah, Al, Bh, Bl, 0, 8);
        if (more) {
            #pragma unroll
            for (int t = 0; t < 8; ++t)
                put2(nh, nl, drow + t*16, mycol, st[t]);
            #pragma unroll
            for (int t = 0; t < 8; ++t)
                st[t] = __ldg(gbase + (size_t)(nb + drow + (8+t)*16) * KPTS);
        }
        span_hl(acc, Ah, Al, Bh, Bl, 8, 16);
        if (more) {
            #pragma unroll
            for (int t = 0; t < 8; ++t)
                put2(nh, nl, drow + (8+t)*16, mycol, st[t]);
        }
        __syncthreads();
    }

    // bias + LN stats
    {
        float bb0 = __ldg(b_proj + m0 + r);
        float bb1 = __ldg(b_proj + m0 + r + 8);
        #pragma unroll
        for (int nt = 0; nt < NTILES; ++nt) {
            acc[nt*4+0] += bb0; acc[nt*4+1] += bb0;
            acc[nt*4+2] += bb1; acc[nt*4+3] += bb1;
        }
    }
    {
        float s[8], q[8];
        #pragma unroll
        for (int nt = 0; nt < NTILES; ++nt) {
            s[nt*2+0] = acc[nt*4+0] + acc[nt*4+2];
            s[nt*2+1] = acc[nt*4+1] + acc[nt*4+3];
            q[nt*2+0] = acc[nt*4+0]*acc[nt*4+0] + acc[nt*4+2]*acc[nt*4+2];
            q[nt*2+1] = acc[nt*4+1]*acc[nt*4+1] + acc[nt*4+3]*acc[nt*4+3];
        }
        #pragma unroll
        for (int off = 4; off < 32; off <<= 1) {
            #pragma unroll
            for (int u = 0; u < 8; ++u) {
                s[u] += __shfl_xor_sync(0xffffffffu, s[u], off);
                q[u] += __shfl_xor_sync(0xffffffffu, q[u], off);
            }
        }
        if (lane < 4) {
            #pragma unroll
            for (int nt = 0; nt < NTILES; ++nt) {
                int col = nt*8 + lane*2;
                red_s[col*16 + wid]     = s[nt*2+0];
                red_s[(col+1)*16 + wid] = s[nt*2+1];
                red_q[col*16 + wid]     = q[nt*2+0];
                red_q[(col+1)*16 + wid] = q[nt*2+1];
            }
        }
    }
    __syncthreads();
    if (tid < COLS_T) {
        float S = 0.0f, Q = 0.0f;
        #pragma unroll
        for (int mt = 0; mt < 16; ++mt) { S += red_s[tid*16+mt]; Q += red_q[tid*16+mt]; }
        float mu  = S * (1.0f/256.0f);
        float var = Q * (1.0f/256.0f) - mu*mu;
        smu[tid] = mu;
        srs[tid] = rsqrtf(var + 1e-5f);
    }
    __syncthreads();

    // normalize -> b0h/b0l (Ba)
    #pragma unroll
    for (int nt = 0; nt < NTILES; ++nt) {
        int col = nt*8 + c2;
        float mA = smu[col],   rA = srs[col];
        float mB = smu[col+1], rB = srs[col+1];
        put2(b0h, b0l, m0+r,   col,   (acc[nt*4+0]-mA)*rA);
        put2(b0h, b0l, m0+r,   col+1, (acc[nt*4+1]-mB)*rB);
        put2(b0h, b0l, m0+r+8, col,   (acc[nt*4+2]-mA)*rA);
        put2(b0h, b0l, m0+r+8, col+1, (acc[nt*4+3]-mB)*rB);
    }
    __syncthreads();

    // adapter conv1 + ReLU -> b1h/b1l
    #pragma unroll
    for (int p = 0; p < 16; ++p) acc[p] = 0.0f;
    {
        const uint4* Ah = (const uint4*)g_A1h + ((size_t)wid*NKS_AH*32 + lane);
        const uint4* Al = (const uint4*)g_A1l + ((size_t)wid*NKS_AH*32 + lane);
        span_hl(acc, Ah, Al, B0h, B0l, 0, 16);
    }
    {
        float bb0 = __ldg(b_a1 + m0 + r);
        float bb1 = __ldg(b_a1 + m0 + r + 8);
        #pragma unroll
        for (int nt = 0; nt < NTILES; ++nt) {
            int col = nt*8 + c2;
            put2(b1h, b1l, m0+r,   col,   fmaxf(acc[nt*4+0]+bb0, 0.0f));
            put2(b1h, b1l, m0+r,   col+1, fmaxf(acc[nt*4+1]+bb0, 0.0f));
            put2(b1h, b1l, m0+r+8, col,   fmaxf(acc[nt*4+2]+bb1, 0.0f));
            put2(b1h, b1l, m0+r+8, col+1, fmaxf(acc[nt*4+3]+bb1, 0.0f));
        }
    }
    __syncthreads();

    // adapter conv2
    #pragma unroll
    for (int p = 0; p < 16; ++p) acc[p] = 0.0f;
    {
        const uint4* Ah = (const uint4*)g_A2h + ((size_t)wid*NKS_AH*32 + lane);
        const uint4* Al = (const uint4*)g_A2l + ((size_t)wid*NKS_AH*32 + lane);
        span_hl(acc, Ah, Al, B1h, B1l, 0, 16);
    }

    // bias + output + loss
    float bb0 = __ldg(b_a2 + m0 + r);
    float bb1 = __ldg(b_a2 + m0 + r + 8);
    float ls = 0.0f;
    size_t ob0 = ((size_t)b * CH + (m0 + r)) * NSEED + ns0;
    size_t ob1 = ((size_t)b * CH + (m0 + r + 8)) * NSEED + ns0;
    bool full = (NFS <= out_size);
    #pragma unroll
    for (int nt = 0; nt < NTILES; ++nt) {
        int col = nt*8 + c2;
        float f0 = acc[nt*4+0]+bb0, f1 = acc[nt*4+1]+bb0;
        float f2 = acc[nt*4+2]+bb1, f3 = acc[nt*4+3]+bb1;
        if (full) {
            *(float2*)(out + ob0 + col) = make_float2(f0, f1);
            *(float2*)(out + ob1 + col) = make_float2(f2, f3);
        }
        float2 t0 = *(const float2*)(f_teacher + ob0 + col);
        float2 t1 = *(const float2*)(f_teacher + ob1 + col);
        float d0 = f0-t0.x, d1 = f1-t0.y, d2 = f2-t1.x, d3 = f3-t1.y;
        ls += d0*d0 + d1*d1 + d2*d2 + d3*d3;
    }
    #pragma unroll
    for (int o = 16; o; o >>= 1) ls += __shfl_xor_sync(0xffffffffu, ls, o);
    if (lane == 0) atomicAdd(&g_loss, ls);
}

// -------------------- kernel 3: finalize loss --------------------
__global__ void k_final(float* __restrict__ out, int out_size)
{
    float v = g_loss * (1.0f / (float)NFS);
    if (out_size > NFS) {
        for (int i = NFS + (int)threadIdx.x; i < out_size; i += (int)blockDim.x)
            out[i] = v;
    } else if (out_size > 0 && out_size < NFS && threadIdx.x == 0) {
        out[out_size - 1] = v;
    }
}

// -------------------- launch --------------------
extern "C" void kernel_launch(void* const* d_in, const int* in_sizes, int n_in,
                              void* d_out, int out_size)
{
    (void)in_sizes; (void)n_in;
    const float* seed_xyz    = (const float*)d_in[1];
    const float* pts         = (const float*)d_in[2];
    const float* feat        = (const float*)d_in[3];
    const float* f_teacher   = (const float*)d_in[4];
    const float* W_proj      = (const float*)d_in[5];
    const float* b_proj      = (const float*)d_in[6];
    const float* W_a1        = (const float*)d_in[7];
    const float* b_a1        = (const float*)d_in[8];
    const float* W_a2        = (const float*)d_in[9];
    const float* b_a2        = (const float*)d_in[10];
    float* out = (float*)d_out;

    cudaFuncSetAttribute(k_fused, cudaFuncAttributeMaxDynamicSharedMemorySize, SMEM_BYTES);

    k_prep<<<PREP_BLOCKS, 256>>>(W_proj, W_a1, W_a2);
    dim3 g1(BNS/256, NSPLIT);
    k_argmin<<<g1, 256>>>(seed_xyz, pts);
    k_fused<<<BNS/COLS_T, THREADS, SMEM_BYTES>>>(feat, f_teacher,
                                                 b_proj, b_a1, b_a2, out, out_size);
    k_final<<<1, 64>>>(out, out_size);
}

// round 17
// speedup vs baseline: 1.0761x; 1.0018x over previous
#include <cuda_runtime.h>
#include <cuda_bf16.h>
#include <cstdint>

#define BATCH 8
#define NSEED 2048
#define KPTS  16384
#define DIM   768
#define CH    256
#define BNS   (BATCH*NSEED)
#define NFS   (BATCH*CH*NSEED)
#define COLS_T 32
#define THREADS 512
#define NKS_PH 48     // proj hi/lo ksteps (K = 768)
#define NKS_AH 16     // adapter hi/lo ksteps (K = 256)
#define NTILES 4
#define NSPLIT 8
#define PREP_PAIRS ((256*768 + 2*256*256)/2)   // 163840
#define PREP_BLOCKS (PREP_PAIRS/256)           // 640

typedef unsigned short ushort_t;

// -------------------- device scratch --------------------
__device__ float g_bestd[NSPLIT*BNS];
__device__ int   g_besti[NSPLIT*BNS];
__device__ float g_loss;
__device__ ushort_t g_Aph[16*NKS_PH*32*4*2];
__device__ ushort_t g_Apl[16*NKS_PH*32*4*2];
__device__ ushort_t g_A1h[16*NKS_AH*32*4*2];
__device__ ushort_t g_A1l[16*NKS_AH*32*4*2];
__device__ ushort_t g_A2h[16*NKS_AH*32*4*2];
__device__ ushort_t g_A2l[16*NKS_AH*32*4*2];

// -------------------- helpers --------------------
__device__ __forceinline__ void split_hilo(float x, ushort_t& h, ushort_t& l) {
    __nv_bfloat16 hb = __float2bfloat16(x);
    __nv_bfloat16 lb = __float2bfloat16(x - __bfloat162float(hb));
    h = __bfloat16_as_ushort(hb);
    l = __bfloat16_as_ushort(lb);
}
__device__ __forceinline__ unsigned long long pack2(float a, float b) {
    unsigned long long r;
    asm("mov.b64 %0, {%1, %2};" : "=l"(r) : "r"(__float_as_uint(a)), "r"(__float_as_uint(b)));
    return r;
}
__device__ __forceinline__ float2 unpack2(unsigned long long v) {
    unsigned int lo, hi;
    asm("mov.b64 {%0, %1}, %2;" : "=r"(lo), "=r"(hi) : "l"(v));
    return make_float2(__uint_as_float(lo), __uint_as_float(hi));
}
__device__ __forceinline__ unsigned long long fma2(unsigned long long a,
                                                   unsigned long long b,
                                                   unsigned long long c) {
    unsigned long long d;
    asm("fma.rn.f32x2 %0, %1, %2, %3;" : "=l"(d) : "l"(a), "l"(b), "l"(c));
    return d;
}

// fragment index for slot s (= dim), output row o
__device__ __forceinline__ size_t aidx_h(int o, int s, int nks) {
    int kstep = s >> 4, ks = s & 15;
    int mtile = o >> 4, mm = o & 15;
    int lane = (mm & 7) * 4 + ((ks >> 1) & 3);
    int word = ((mm >> 3) & 1) + 2 * ((ks >> 3) & 1);
    int half = ks & 1;
    return ((((size_t)mtile * nks + kstep) * 32 + lane) * 4 + word) * 2 + half;
}
__device__ __forceinline__ int bidx_h(int s, int n) {
    int kstep = s >> 4, ks = s & 15;
    int nt = n >> 3, np = nt >> 1, ntip = nt & 1;
    int lane = (n & 7) * 4 + ((ks >> 1) & 3);
    int wk = (ks >> 3) & 1;
    int half = ks & 1;
    return (((kstep * 2 + np) * 32 + lane) * 4 + (ntip * 2 + wk)) * 2 + half;
}
__device__ __forceinline__ void put2(ushort_t* bh, ushort_t* bl, int row, int col, float v) {
    ushort_t h, l; split_hilo(v, h, l);
    int ix = bidx_h(row, col);
    bh[ix] = h;
    bl[ix] = l;
}

// -------------------- weight prep: word-packed (dim pairs) --------------------
__global__ __launch_bounds__(256) void k_prep(
    const float* __restrict__ Wp, const float* __restrict__ Wa1, const float* __restrict__ Wa2)
{
    int id = blockIdx.x * 256 + threadIdx.x;     // pair index
    if (id == 0) g_loss = 0.0f;
    int e = id * 2;
    ushort_t h0, l0, h1, l1;
    if (e < 256*768) {
        int o = e / 768, d = e % 768;            // d even
        float2 w = *(const float2*)(Wp + e);
        split_hilo(w.x, h0, l0);
        split_hilo(w.y, h1, l1);
        size_t wi = aidx_h(o, d, NKS_PH) >> 1;
        ((unsigned*)g_Aph)[wi] = (unsigned)h0 | ((unsigned)h1 << 16);
        ((unsigned*)g_Apl)[wi] = (unsigned)l0 | ((unsigned)l1 << 16);
    } else if (e < 256*768 + 256*256) {
        int t = e - 256*768; int o = t >> 8, d = t & 255;
        float2 w = *(const float2*)(Wa1 + t);
        split_hilo(w.x, h0, l0);
        split_hilo(w.y, h1, l1);
        size_t wi = aidx_h(o, d, NKS_AH) >> 1;
        ((unsigned*)g_A1h)[wi] = (unsigned)h0 | ((unsigned)h1 << 16);
        ((unsigned*)g_A1l)[wi] = (unsigned)l0 | ((unsigned)l1 << 16);
    } else if (e < 256*768 + 2*256*256) {
        int t = e - 256*768 - 256*256; int o = t >> 8, d = t & 255;
        float2 w = *(const float2*)(Wa2 + t);
        split_hilo(w.x, h0, l0);
        split_hilo(w.y, h1, l1);
        size_t wi = aidx_h(o, d, NKS_AH) >> 1;
        ((unsigned*)g_A2h)[wi] = (unsigned)h0 | ((unsigned)h1 << 16);
        ((unsigned*)g_A2l)[wi] = (unsigned)l0 | ((unsigned)l1 << 16);
    }
}

// -------------------- kernel 1: argmin, 256 seeds/block, packed-operand loads --------------------
__global__ __launch_bounds__(256) void k_argmin(
    const float* __restrict__ seed, const float* __restrict__ pts)
{
    __shared__ float4 tA[1024], tB[1024];   // (x0,x1,y0,y1) / (z0,z1,|p0|^2,|p1|^2)
    int gs = blockIdx.x * 256 + threadIdx.x;
    int b  = gs >> 11;
    int kbase = blockIdx.y * 2048;
    const float* pb = pts + ((size_t)b * KPTS + kbase) * 3;

    float sx = seed[gs*3+0], sy = seed[gs*3+1], sz = seed[gs*3+2];
    unsigned long long mxx = pack2(-2.0f*sx, -2.0f*sx);
    unsigned long long myy = pack2(-2.0f*sy, -2.0f*sy);
    unsigned long long mzz = pack2(-2.0f*sz, -2.0f*sz);

    for (int p = threadIdx.x; p < 1024; p += 256) {
        const float* q = pb + 6*p;
        float x0=q[0], y0=q[1], z0=q[2], x1=q[3], y1=q[4], z1=q[5];
        tA[p] = make_float4(x0, x1, y0, y1);
        tB[p] = make_float4(z0, z1, x0*x0+y0*y0+z0*z0, x1*x1+y1*y1+z1*z1);
    }
    __syncthreads();

    const ulonglong2* uA = (const ulonglong2*)tA;
    const ulonglong2* uB = (const ulonglong2*)tB;

    float bd = 1e30f;
    int gwin = 0;
    #pragma unroll 1
    for (int g = 0; g < 16; ++g) {
        float gbd = bd;
        const ulonglong2* pA = uA + g*64;
        const ulonglong2* pB = uB + g*64;
        #pragma unroll 8
        for (int it = 0; it < 64; ++it) {
            ulonglong2 U = pA[it];
            ulonglong2 V = pB[it];
            unsigned long long d2 = fma2(mxx, U.x, fma2(myy, U.y, fma2(mzz, V.x, V.y)));
            float2 d = unpack2(d2);
            gbd = fminf(gbd, fminf(d.x, d.y));
        }
        if (gbd < bd) { bd = gbd; gwin = g; }
    }

    int lane = threadIdx.x & 31;
    int mi = 0x7fffffff;
    int base = gwin * 64;
    #pragma unroll 8
    for (int it = 0; it < 64; ++it) {
        int p = base + ((it + lane) & 63);
        ulonglong2 U = uA[p];
        ulonglong2 V = uB[p];
        unsigned long long d2 = fma2(mxx, U.x, fma2(myy, U.y, fma2(mzz, V.x, V.y)));
        float2 d = unpack2(d2);
        if (d.x == bd) mi = min(mi, 2*p);
        if (d.y == bd) mi = min(mi, 2*p + 1);
    }
    g_bestd[blockIdx.y * BNS + gs] = bd;
    g_besti[blockIdx.y * BNS + gs] = kbase + mi;
}

// -------------------- mma helpers --------------------
__device__ __forceinline__ void mma16816(float* c, const uint4& a, unsigned b0, unsigned b1) {
    asm volatile(
        "mma.sync.aligned.m16n8k16.row.col.f32.bf16.bf16.f32 "
        "{%0,%1,%2,%3}, {%4,%5,%6,%7}, {%8,%9}, {%0,%1,%2,%3};"
        : "+f"(c[0]), "+f"(c[1]), "+f"(c[2]), "+f"(c[3])
        : "r"(a.x), "r"(a.y), "r"(a.z), "r"(a.w), "r"(b0), "r"(b1));
}
// Fused hi+lo span (round-16 winner): per kstep load Bh/Bl once, 12 MMAs.
__device__ __forceinline__ void span_hl(float acc[16],
    const uint4* __restrict__ Ah, const uint4* __restrict__ Al,
    const uint4* __restrict__ Bh, const uint4* __restrict__ Bl,
    int ks0, int ks1)
{
    uint4 ah[2], al[2];
    ah[0] = Ah[(size_t)ks0*32];       ah[1] = Ah[(size_t)(ks0+1)*32];
    al[0] = Al[(size_t)ks0*32];       al[1] = Al[(size_t)(ks0+1)*32];
    #pragma unroll 1
    for (int kb = ks0; kb < ks1; kb += 2) {
        uint4 nh[2], nl[2];
        bool more = (kb + 2) < ks1;
        if (more) {
            nh[0] = Ah[(size_t)(kb+2)*32]; nh[1] = Ah[(size_t)(kb+3)*32];
            nl[0] = Al[(size_t)(kb+2)*32]; nl[1] = Al[(size_t)(kb+3)*32];
        }
        #pragma unroll
        for (int j = 0; j < 2; ++j) {
            int ks = kb + j;
            uint4 b0 = Bh[(ks*2 + 0) * 32];
            uint4 b1 = Bh[(ks*2 + 1) * 32];
            uint4 c0 = Bl[(ks*2 + 0) * 32];
            uint4 c1 = Bl[(ks*2 + 1) * 32];
            mma16816(acc + 0,  ah[j], b0.x, b0.y);
            mma16816(acc + 4,  ah[j], b0.z, b0.w);
            mma16816(acc + 8,  ah[j], b1.x, b1.y);
            mma16816(acc + 12, ah[j], b1.z, b1.w);
            mma16816(acc + 0,  ah[j], c0.x, c0.y);
            mma16816(acc + 4,  ah[j], c0.z, c0.w);
            mma16816(acc + 8,  ah[j], c1.x, c1.y);
            mma16816(acc + 12, ah[j], c1.z, c1.w);
            mma16816(acc + 0,  al[j], b0.x, b0.y);
            mma16816(acc + 4,  al[j], b0.z, b0.w);
            mma16816(acc + 8,  al[j], b1.x, b1.y);
            mma16816(acc + 12, al[j], b1.z, b1.w);
        }
        ah[0] = nh[0]; ah[1] = nh[1];
        al[0] = nl[0]; al[1] = nl[1];
    }
}

// -------------------- smem layout (bytes) --------------------
#define SMB_B0H  0
#define SMB_B0L  16384
#define SMB_B1H  32768
#define SMB_B1L  49152
#define SMB_REDS 65536
#define SMB_REDQ 67584
#define SMB_MU   69632
#define SMB_RS   69760
#define SMEM_BYTES 69888

// -------------------- kernel 2: fused (identical to round 16) --------------------
__global__ void __launch_bounds__(THREADS, 1) k_fused(
    const float* __restrict__ feat, const float* __restrict__ f_teacher,
    const float* __restrict__ b_proj, const float* __restrict__ b_a1,
    const float* __restrict__ b_a2,
    float* __restrict__ out, int out_size)
{
    extern __shared__ char smraw[];
    ushort_t* b0h = (ushort_t*)(smraw + SMB_B0H);
    ushort_t* b0l = (ushort_t*)(smraw + SMB_B0L);
    ushort_t* b1h = (ushort_t*)(smraw + SMB_B1H);
    ushort_t* b1l = (ushort_t*)(smraw + SMB_B1L);
    float* red_s = (float*)(smraw + SMB_REDS);
    float* red_q = (float*)(smraw + SMB_REDQ);
    float* smu   = (float*)(smraw + SMB_MU);
    float* srs   = (float*)(smraw + SMB_RS);

    int tid  = threadIdx.x;
    int lane = tid & 31;
    int wid  = tid >> 5;
    int j0   = blockIdx.x * COLS_T;
    int b    = j0 >> 11;
    int ns0  = j0 & 2047;

    // per-thread split-K merge (no barrier)
    int mycol = tid & 31;
    int drow  = tid >> 5;
    int bi;
    {
        int gs = j0 + mycol;
        float bd = g_bestd[gs];
        bi = g_besti[gs];
        #pragma unroll
        for (int y = 1; y < NSPLIT; ++y) {
            float d2 = g_bestd[y*BNS + gs];
            int   i2 = g_besti[y*BNS + gs];
            if (d2 < bd || (d2 == bd && i2 < bi)) { bd = d2; bi = i2; }
        }
    }
    const float* featb = feat + (size_t)b * DIM * KPTS;
    const float* gbase = featb + bi;

    // chunk 0 gather -> b0h/b0l
    {
        float v[16];
        #pragma unroll
        for (int t = 0; t < 16; ++t)
            v[t] = __ldg(gbase + (size_t)(drow + t*16) * KPTS);
        #pragma unroll
        for (int t = 0; t < 16; ++t)
            put2(b0h, b0l, drow + t*16, mycol, v[t]);
    }
    __syncthreads();

    int r  = lane >> 2;
    int c2 = (lane & 3) * 2;
    int m0 = wid * 16;

    float acc[16];
    #pragma unroll
    for (int p = 0; p < 16; ++p) acc[p] = 0.0f;

    const uint4* Aph = (const uint4*)g_Aph + ((size_t)wid*NKS_PH*32 + lane);
    const uint4* Apl = (const uint4*)g_Apl + ((size_t)wid*NKS_PH*32 + lane);
    const uint4* B0h = (const uint4*)b0h + lane;
    const uint4* B0l = (const uint4*)b0l + lane;
    const uint4* B1h = (const uint4*)b1h + lane;
    const uint4* B1l = (const uint4*)b1l + lane;

    // projection: 3 chunks of 256 dims (16 ksteps fused hi+lo), pipelined gather
    #pragma unroll 1
    for (int c = 0; c < 3; ++c) {
        const uint4* Bh = (c & 1) ? B1h : B0h;
        const uint4* Bl = (c & 1) ? B1l : B0l;
        ushort_t* nh = (c & 1) ? b0h : b1h;
        ushort_t* nl = (c & 1) ? b0l : b1l;
        const uint4* Ah = Aph + (size_t)c*16*32;
        const uint4* Al = Apl + (size_t)c*16*32;
        bool more = (c < 2);
        int nb = (c+1)*256;
        float st[8];
        if (more) {
            #pragma unroll
            for (int t = 0; t < 8; ++t)
                st[t] = __ldg(gbase + (size_t)(nb + drow + t*16) * KPTS);
        }
        span_hl(acc, Ah, Al, Bh, Bl, 0, 8);
        if (more) {
            #pragma unroll
            for (int t = 0; t < 8; ++t)
                put2(nh, nl, drow + t*16, mycol, st[t]);
            #pragma unroll
            for (int t = 0; t < 8; ++t)
                st[t] = __ldg(gbase + (size_t)(nb + drow + (8+t)*16) * KPTS);
        }
        span_hl(acc, Ah, Al, Bh, Bl, 8, 16);
        if (more) {
            #pragma unroll
            for (int t = 0; t < 8; ++t)
                put2(nh, nl, drow + (8+t)*16, mycol, st[t]);
        }
        __syncthreads();
    }

    // bias + LN stats
    {
        float bb0 = __ldg(b_proj + m0 + r);
        float bb1 = __ldg(b_proj + m0 + r + 8);
        #pragma unroll
        for (int nt = 0; nt < NTILES; ++nt) {
            acc[nt*4+0] += bb0; acc[nt*4+1] += bb0;
            acc[nt*4+2] += bb1; acc[nt*4+3] += bb1;
        }
    }
    {
        float s[8], q[8];
        #pragma unroll
        for (int nt = 0; nt < NTILES; ++nt) {
            s[nt*2+0] = acc[nt*4+0] + acc[nt*4+2];
            s[nt*2+1] = acc[nt*4+1] + acc[nt*4+3];
            q[nt*2+0] = acc[nt*4+0]*acc[nt*4+0] + acc[nt*4+2]*acc[nt*4+2];
            q[nt*2+1] = acc[nt*4+1]*acc[nt*4+1] + acc[nt*4+3]*acc[nt*4+3];
        }
        #pragma unroll
        for (int off = 4; off < 32; off <<= 1) {
            #pragma unroll
            for (int u = 0; u < 8; ++u) {
                s[u] += __shfl_xor_sync(0xffffffffu, s[u], off);
                q[u] += __shfl_xor_sync(0xffffffffu, q[u], off);
            }
        }
        if (lane < 4) {
            #pragma unroll
            for (int nt = 0; nt < NTILES; ++nt) {
                int col = nt*8 + lane*2;
                red_s[col*16 + wid]     = s[nt*2+0];
                red_s[(col+1)*16 + wid] = s[nt*2+1];
                red_q[col*16 + wid]     = q[nt*2+0];
                red_q[(col+1)*16 + wid] = q[nt*2+1];
            }
        }
    }
    __syncthreads();
    if (tid < COLS_T) {
        float S = 0.0f, Q = 0.0f;
        #pragma unroll
        for (int mt = 0; mt < 16; ++mt) { S += red_s[tid*16+mt]; Q += red_q[tid*16+mt]; }
        float mu  = S * (1.0f/256.0f);
        float var = Q * (1.0f/256.0f) - mu*mu;
        smu[tid] = mu;
        srs[tid] = rsqrtf(var + 1e-5f);
    }
    __syncthreads();

    // normalize -> b0h/b0l (Ba)
    #pragma unroll
    for (int nt = 0; nt < NTILES; ++nt) {
        int col = nt*8 + c2;
        float mA = smu[col],   rA = srs[col];
        float mB = smu[col+1], rB = srs[col+1];
        put2(b0h, b0l, m0+r,   col,   (acc[nt*4+0]-mA)*rA);
        put2(b0h, b0l, m0+r,   col+1, (acc[nt*4+1]-mB)*rB);
        put2(b0h, b0l, m0+r+8, col,   (acc[nt*4+2]-mA)*rA);
        put2(b0h, b0l, m0+r+8, col+1, (acc[nt*4+3]-mB)*rB);
    }
    __syncthreads();

    // adapter conv1 + ReLU -> b1h/b1l
    #pragma unroll
    for (int p = 0; p < 16; ++p) acc[p] = 0.0f;
    {
        const uint4* Ah = (const uint4*)g_A1h + ((size_t)wid*NKS_AH*32 + lane);
        const uint4* Al = (const uint4*)g_A1l + ((size_t)wid*NKS_AH*32 + lane);
        span_hl(acc, Ah, Al, B0h, B0l, 0, 16);
    }
    {
        float bb0 = __ldg(b_a1 + m0 + r);
        float bb1 = __ldg(b_a1 + m0 + r + 8);
        #pragma unroll
        for (int nt = 0; nt < NTILES; ++nt) {
            int col = nt*8 + c2;
            put2(b1h, b1l, m0+r,   col,   fmaxf(acc[nt*4+0]+bb0, 0.0f));
            put2(b1h, b1l, m0+r,   col+1, fmaxf(acc[nt*4+1]+bb0, 0.0f));
            put2(b1h, b1l, m0+r+8, col,   fmaxf(acc[nt*4+2]+bb1, 0.0f));
            put2(b1h, b1l, m0+r+8, col+1, fmaxf(acc[nt*4+3]+bb1, 0.0f));
        }
    }
    __syncthreads();

    // adapter conv2
    #pragma unroll
    for (int p = 0; p < 16; ++p) acc[p] = 0.0f;
    {
        const uint4* Ah = (const uint4*)g_A2h + ((size_t)wid*NKS_AH*32 + lane);
        const uint4* Al = (const uint4*)g_A2l + ((size_t)wid*NKS_AH*32 + lane);
        span_hl(acc, Ah, Al, B1h, B1l, 0, 16);
    }

    // bias + output + loss
    float bb0 = __ldg(b_a2 + m0 + r);
    float bb1 = __ldg(b_a2 + m0 + r + 8);
    float ls = 0.0f;
    size_t ob0 = ((size_t)b * CH + (m0 + r)) * NSEED + ns0;
    size_t ob1 = ((size_t)b * CH + (m0 + r + 8)) * NSEED + ns0;
    bool full = (NFS <= out_size);
    #pragma unroll
    for (int nt = 0; nt < NTILES; ++nt) {
        int col = nt*8 + c2;
        float f0 = acc[nt*4+0]+bb0, f1 = acc[nt*4+1]+bb0;
        float f2 = acc[nt*4+2]+bb1, f3 = acc[nt*4+3]+bb1;
        if (full) {
            *(float2*)(out + ob0 + col) = make_float2(f0, f1);
            *(float2*)(out + ob1 + col) = make_float2(f2, f3);
        }
        float2 t0 = *(const float2*)(f_teacher + ob0 + col);
        float2 t1 = *(const float2*)(f_teacher + ob1 + col);
        float d0 = f0-t0.x, d1 = f1-t0.y, d2 = f2-t1.x, d3 = f3-t1.y;
        ls += d0*d0 + d1*d1 + d2*d2 + d3*d3;
    }
    #pragma unroll
    for (int o = 16; o; o >>= 1) ls += __shfl_xor_sync(0xffffffffu, ls, o);
    if (lane == 0) atomicAdd(&g_loss, ls);
}

// -------------------- kernel 3: finalize loss --------------------
__global__ void k_final(float* __restrict__ out, int out_size)
{
    float v = g_loss * (1.0f / (float)NFS);
    if (out_size > NFS) {
        for (int i = NFS + (int)threadIdx.x; i < out_size; i += (int)blockDim.x)
            out[i] = v;
    } else if (out_size > 0 && out_size < NFS && threadIdx.x == 0) {
        out[out_size - 1] = v;
    }
}

// -------------------- launch --------------------
extern "C" void kernel_launch(void* const* d_in, const int* in_sizes, int n_in,
                              void* d_out, int out_size)
{
    (void)in_sizes; (void)n_in;
    const float* seed_xyz    = (const float*)d_in[1];
    const float* pts         = (const float*)d_in[2];
    const float* feat        = (const float*)d_in[3];
    const float* f_teacher   = (const float*)d_in[4];
    const float* W_proj      = (const float*)d_in[5];
    const float* b_proj      = (const float*)d_in[6];
    const float* W_a1        = (const float*)d_in[7];
    const float* b_a1        = (const float*)d_in[8];
    const float* W_a2        = (const float*)d_in[9];
    const float* b_a2        = (const float*)d_in[10];
    float* out = (float*)d_out;

    cudaFuncSetAttribute(k_fused, cudaFuncAttributeMaxDynamicSharedMemorySize, SMEM_BYTES);

    k_prep<<<PREP_BLOCKS, 256>>>(W_proj, W_a1, W_a2);
    dim3 g1(BNS/256, NSPLIT);
    k_argmin<<<g1, 256>>>(seed_xyz, pts);
    k_fused<<<BNS/COLS_T, THREADS, SMEM_BYTES>>>(feat, f_teacher,
                                                 b_proj, b_a1, b_a2, out, out_size);
    k_final<<<1, 64>>>(out, out_size);
}